// round 14
// baseline (speedup 1.0000x reference)
#include <cuda_runtime.h>
#include <math.h>

#define FF    128
#define F3    384
#define NRBF  20
#define AMAX  50000
#define EMAX  500000
#define PI_F  3.14159265358979323846f
#define RCUT  5.0f
#define KPI   (PI_F / RCUT)

typedef unsigned long long u64;

// scratch (device globals: allocation-free; BSS-zeroed at module load)
__device__ float g_sbuf[AMAX * F3];     // node MLP output [A,384]
__device__ int   g_cnt[AMAX];           // zeroed by scan_kernel after use
__device__ int   g_cur[AMAX];
__device__ int   g_ii[EMAX];
__device__ int   g_jj[EMAX];
__device__ float g_dir[EMAX * 3];

// ---- packed fp32x2 helpers -------------------------------------------------
__device__ __forceinline__ u64 pk2(float lo, float hi) {
    u64 r; asm("mov.b64 %0, {%1, %2};" : "=l"(r) : "f"(lo), "f"(hi)); return r;
}
__device__ __forceinline__ u64 fma2(u64 a, u64 b, u64 c) {
    u64 d; asm("fma.rn.f32x2 %0, %1, %2, %3;" : "=l"(d) : "l"(a), "l"(b), "l"(c));
    return d;
}
__device__ __forceinline__ float2 upk2(u64 v) {
    float2 f; asm("mov.b64 {%0, %1}, %2;" : "=f"(f.x), "=f"(f.y) : "l"(v)); return f;
}

// ---------------------------------------------------------------------------
__global__ void hist_kernel(const int* __restrict__ idx_i, int E) {
    int e = blockIdx.x * blockDim.x + threadIdx.x;
    if (e < E) atomicAdd(&g_cnt[idx_i[e]], 1);
}

// single-block exclusive scan over g_cnt -> g_cur (1024 threads).
// Also ZEROES g_cnt after reading (removes the per-call memset launch;
// g_cnt is BSS-zero at load, so the invariant holds across graph replays).
__global__ __launch_bounds__(1024) void scan_kernel(int A) {
    __shared__ int wsum[32];
    __shared__ int s_carry;
    const int tid = threadIdx.x, lane = tid & 31, w = tid >> 5;
    if (tid == 0) s_carry = 0;
    __syncthreads();
    for (int base = 0; base < A; base += 1024) {
        int v = 0;
        if (base + tid < A) {
            v = g_cnt[base + tid];
            g_cnt[base + tid] = 0;
        }
        int incl = v;
#pragma unroll
        for (int d = 1; d < 32; d <<= 1) {
            int t = __shfl_up_sync(0xffffffffu, incl, d);
            if (lane >= d) incl += t;
        }
        if (lane == 31) wsum[w] = incl;
        __syncthreads();
        if (w == 0) {
            int s = wsum[lane];
#pragma unroll
            for (int d = 1; d < 32; d <<= 1) {
                int t = __shfl_up_sync(0xffffffffu, s, d);
                if (lane >= d) s += t;
            }
            wsum[lane] = s;
        }
        __syncthreads();
        int blockIncl = incl + (w > 0 ? wsum[w - 1] : 0);
        int carry = s_carry;
        if (base + tid < A) g_cur[base + tid] = carry + blockIncl - v;
        __syncthreads();
        if (tid == 1023) s_carry = carry + blockIncl;
        __syncthreads();
    }
}

__global__ void scatter_kernel(const int* __restrict__ idx_i,
                               const int* __restrict__ idx_j,
                               const float* __restrict__ directions, int E) {
    int e = blockIdx.x * blockDim.x + threadIdx.x;
    if (e >= E) return;
    int i = idx_i[e];
    int pos = atomicAdd(&g_cur[i], 1);
    g_ii[pos] = i;
    g_jj[pos] = idx_j[e];
    g_dir[(size_t)pos * 3 + 0] = directions[(size_t)e * 3 + 0];
    g_dir[(size_t)pos * 3 + 1] = directions[(size_t)e * 3 + 1];
    g_dir[(size_t)pos * 3 + 2] = directions[(size_t)e * 3 + 2];
}

// ---------------------------------------------------------------------------
// Node MLP: verbatim from the 575.7us champion.
__global__ __launch_bounds__(256, 2) void mlp_kernel(
    const float* __restrict__ scalars, const float* __restrict__ W1,
    const float* __restrict__ b1, const float* __restrict__ W2,
    const float* __restrict__ b2, int A)
{
    __shared__ float sx[16][FF];
    __shared__ float sh[16][FF];
    const int row0 = blockIdx.x * 16;
    const int tid  = threadIdx.x;

    for (int idx = tid; idx < 16 * 32; idx += 256) {
        int m = idx >> 5, c = idx & 31;
        float4 v = make_float4(0.f, 0.f, 0.f, 0.f);
        if (row0 + m < A)
            v = reinterpret_cast<const float4*>(scalars)[(size_t)(row0 + m) * 32 + c];
        *reinterpret_cast<float4*>(&sx[m][c * 4]) = v;
    }
    __syncthreads();

    const int n  = tid & 127;
    const int m0 = (tid >> 7) * 8;

    u64 acc[8];
#pragma unroll
    for (int i = 0; i < 8; i++) acc[i] = 0ull;

    for (int k = 0; k < FF; k += 4) {
        u64 wp0 = pk2(W1[(k + 0) * FF + n], W1[(k + 1) * FF + n]);
        u64 wp1 = pk2(W1[(k + 2) * FF + n], W1[(k + 3) * FF + n]);
#pragma unroll
        for (int i = 0; i < 8; i++) {
            ulonglong2 x2 = *reinterpret_cast<const ulonglong2*>(&sx[m0 + i][k]);
            acc[i] = fma2(x2.x, wp0, acc[i]);
            acc[i] = fma2(x2.y, wp1, acc[i]);
        }
    }
    {
        float bb = b1[n];
#pragma unroll
        for (int i = 0; i < 8; i++) {
            float2 p = upk2(acc[i]);
            float x = p.x + p.y + bb;
            sh[m0 + i][n] = x / (1.f + __expf(-x));
        }
    }
    __syncthreads();

    u64 a2[8][3];
#pragma unroll
    for (int i = 0; i < 8; i++)
#pragma unroll
        for (int c = 0; c < 3; c++) a2[i][c] = 0ull;

    for (int k = 0; k < FF; k += 4) {
        u64 wp[3][2];
#pragma unroll
        for (int c = 0; c < 3; c++) {
            wp[c][0] = pk2(W2[(k + 0) * F3 + n + c * 128], W2[(k + 1) * F3 + n + c * 128]);
            wp[c][1] = pk2(W2[(k + 2) * F3 + n + c * 128], W2[(k + 3) * F3 + n + c * 128]);
        }
#pragma unroll
        for (int i = 0; i < 8; i++) {
            ulonglong2 h2 = *reinterpret_cast<const ulonglong2*>(&sh[m0 + i][k]);
#pragma unroll
            for (int c = 0; c < 3; c++) {
                a2[i][c] = fma2(h2.x, wp[c][0], a2[i][c]);
                a2[i][c] = fma2(h2.y, wp[c][1], a2[i][c]);
            }
        }
    }
    {
        float c0 = b2[n], c1 = b2[n + 128], c2v = b2[n + 256];
#pragma unroll
        for (int i = 0; i < 8; i++) {
            int row = row0 + m0 + i;
            if (row < A) {
                float2 p0 = upk2(a2[i][0]);
                float2 p1 = upk2(a2[i][1]);
                float2 p2 = upk2(a2[i][2]);
                g_sbuf[(size_t)row * F3 + n]       = p0.x + p0.y + c0;
                g_sbuf[(size_t)row * F3 + n + 128] = p1.x + p1.y + c1;
                g_sbuf[(size_t)row * F3 + n + 256] = p2.x + p2.y + c2v;
            }
        }
    }
}

// ---------------------------------------------------------------------------
__device__ __forceinline__ void red4(float* p, float4 v) {
    asm volatile("red.global.add.v4.f32 [%0], {%1, %2, %3, %4};"
                 :: "l"(p), "f"(v.x), "f"(v.y), "f"(v.z), "f"(v.w)
                 : "memory");
}

#define EPW 4   // edges per warp

// Edge kernel over i-sorted edges: verbatim from the 575.7us champion.
__global__ __launch_bounds__(256, 2) void edge_kernel(
    const float* __restrict__ vectors,
    const float* __restrict__ Wr, const float* __restrict__ br,
    float* __restrict__ out_v, float* __restrict__ out_s, int E)
{
    __shared__ float4 swr[NRBF * 96];   // Wr [20][384] as float4
    __shared__ float  sbr[F3];

    const int tid = threadIdx.x;
    for (int i2 = tid; i2 < NRBF * 96; i2 += 256)
        swr[i2] = reinterpret_cast<const float4*>(Wr)[i2];
    for (int i2 = tid; i2 < F3; i2 += 256) sbr[i2] = br[i2];
    __syncthreads();

    const int warp = tid >> 5;
    const int lane = tid & 31;
    const int ebase = (blockIdx.x * 8 + warp) * EPW;

    float d0[EPW], d1[EPW], d2[EPW], inv[EPW], fc[EPW], c2r[EPW], scur[EPW], sprev[EPW];
    int   ii[EPW], jj[EPW];
    bool  val[EPW];

#pragma unroll
    for (int e = 0; e < EPW; e++) {
        int ee = ebase + e;
        val[e] = (ee < E);
        d0[e] = 1.f; d1[e] = 0.f; d2[e] = 0.f; ii[e] = 0; jj[e] = 0;
        if (val[e]) {
            d0[e] = g_dir[(size_t)ee * 3 + 0];
            d1[e] = g_dir[(size_t)ee * 3 + 1];
            d2[e] = g_dir[(size_t)ee * 3 + 2];
            ii[e] = g_ii[ee];
            jj[e] = g_jj[ee];
        }
        float nrm = sqrtf(d0[e] * d0[e] + d1[e] * d1[e] + d2[e] * d2[e]);
        inv[e] = 1.f / nrm;
        float x = KPI * nrm;
        float s1, c1;
        __sincosf(x, &s1, &c1);
        c2r[e]   = 2.f * c1;
        scur[e]  = s1;
        sprev[e] = 0.f;
        float delta = nrm - RCUT;
        float mask  = fminf(delta, 0.f) / delta;
        fc[e] = 0.5f * (c1 + 1.f) * mask;
    }

    ulonglong2 aA[EPW], aB[EPW], aC[EPW];
#pragma unroll
    for (int e = 0; e < EPW; e++) {
        aA[e] = make_ulonglong2(0ull, 0ull);
        aB[e] = make_ulonglong2(0ull, 0ull);
        aC[e] = make_ulonglong2(0ull, 0ull);
    }

#pragma unroll
    for (int k = 0; k < NRBF; k++) {
        ulonglong2 wA = *reinterpret_cast<const ulonglong2*>(&swr[k * 96 + lane]);
        ulonglong2 wB = *reinterpret_cast<const ulonglong2*>(&swr[k * 96 + 32 + lane]);
        ulonglong2 wC = *reinterpret_cast<const ulonglong2*>(&swr[k * 96 + 64 + lane]);
#pragma unroll
        for (int e = 0; e < EPW; e++) {
            float s = scur[e];
            u64 sd = pk2(s, s);
            aA[e].x = fma2(wA.x, sd, aA[e].x);
            aA[e].y = fma2(wA.y, sd, aA[e].y);
            aB[e].x = fma2(wB.x, sd, aB[e].x);
            aB[e].y = fma2(wB.y, sd, aB[e].y);
            aC[e].x = fma2(wC.x, sd, aC[e].x);
            aC[e].y = fma2(wC.y, sd, aC[e].y);
            float t = c2r[e] * s - sprev[e];
            sprev[e] = s;
            scur[e]  = t;
        }
    }

    const int f4 = lane * 4;
    float4 brA = *reinterpret_cast<const float4*>(&sbr[f4]);
    float4 brB = *reinterpret_cast<const float4*>(&sbr[128 + f4]);
    float4 brC = *reinterpret_cast<const float4*>(&sbr[256 + f4]);

#pragma unroll
    for (int e = 0; e < EPW; e++) {
        if (!val[e]) continue;
        float f  = fc[e];
        float sc = f * inv[e];

        float2 pAx = upk2(aA[e].x), pAy = upk2(aA[e].y);
        float2 pBx = upk2(aB[e].x), pBy = upk2(aB[e].y);
        float2 pCx = upk2(aC[e].x), pCy = upk2(aC[e].y);

        float4 rA, rB, rC;
        rA.x = sc * pAx.x + f * brA.x; rA.y = sc * pAx.y + f * brA.y;
        rA.z = sc * pAy.x + f * brA.z; rA.w = sc * pAy.y + f * brA.w;
        rB.x = sc * pBx.x + f * brB.x; rB.y = sc * pBx.y + f * brB.y;
        rB.z = sc * pBy.x + f * brB.z; rB.w = sc * pBy.y + f * brB.w;
        rC.x = sc * pCx.x + f * brC.x; rC.y = sc * pCx.y + f * brC.y;
        rC.z = sc * pCy.x + f * brC.z; rC.w = sc * pCy.y + f * brC.w;

        size_t ib = (size_t)ii[e] * F3 + f4;
        float4 sA = *reinterpret_cast<const float4*>(&g_sbuf[ib]);
        float4 sB = *reinterpret_cast<const float4*>(&g_sbuf[ib + 128]);
        float4 sC = *reinterpret_cast<const float4*>(&g_sbuf[ib + 256]);

        float4 ds, dv1, dv2;
        ds.x  = sA.x * rA.x; ds.y  = sA.y * rA.y; ds.z  = sA.z * rA.z; ds.w  = sA.w * rA.w;
        dv1.x = sB.x * rB.x; dv1.y = sB.y * rB.y; dv1.z = sB.z * rB.z; dv1.w = sB.w * rB.w;
        dv2.x = sC.x * rC.x; dv2.y = sC.y * rC.y; dv2.z = sC.z * rC.z; dv2.w = sC.w * rC.w;

        red4(out_s + (size_t)jj[e] * FF + f4, ds);

        float dh[3];
        dh[0] = d0[e] * inv[e]; dh[1] = d1[e] * inv[e]; dh[2] = d2[e] * inv[e];

        size_t vb = (size_t)ii[e] * F3 + f4;
        size_t ob = (size_t)jj[e] * F3 + f4;
#pragma unroll
        for (int d = 0; d < 3; d++) {
            float4 vv = *reinterpret_cast<const float4*>(&vectors[vb + d * 128]);
            float4 ct;
            ct.x = vv.x * dv1.x + dv2.x * dh[d];
            ct.y = vv.y * dv1.y + dv2.y * dh[d];
            ct.z = vv.z * dv1.z + dv2.z * dh[d];
            ct.w = vv.w * dv1.w + dv2.w * dh[d];
            red4(out_v + ob + d * 128, ct);
        }
    }
}

// ---------------------------------------------------------------------------
extern "C" void kernel_launch(void* const* d_in, const int* in_sizes, int n_in,
                              void* d_out, int out_size) {
    const float* vectors    = (const float*)d_in[0];
    const float* scalars    = (const float*)d_in[1];
    const float* directions = (const float*)d_in[2];
    const int*   idx_i      = (const int*)d_in[3];
    const int*   idx_j      = (const int*)d_in[4];
    const float* W1         = (const float*)d_in[5];
    const float* b1         = (const float*)d_in[6];
    const float* W2         = (const float*)d_in[7];
    const float* b2         = (const float*)d_in[8];
    const float* Wr         = (const float*)d_in[9];
    const float* br         = (const float*)d_in[10];

    const int A = in_sizes[0] / (3 * FF);
    const int E = in_sizes[2] / 3;

    float* out   = (float*)d_out;
    float* out_v = out;                          // delta_v: A x 3 x F
    float* out_s = out + (size_t)A * 3 * FF;     // delta_s: A x 1 x F

    static cudaStream_t s2 = nullptr;
    static cudaEvent_t ev0 = nullptr, ev1 = nullptr;
    if (!s2) {
        cudaStreamCreateWithFlags(&s2, cudaStreamNonBlocking);
        cudaEventCreateWithFlags(&ev0, cudaEventDisableTiming);
        cudaEventCreateWithFlags(&ev1, cudaEventDisableTiming);
    }

    // Launch order (6 launches total; edge = #6 -> lands in ncu's -s 5 window):
    //   1 memset(out, main), 2 hist(s2), 3 scan(s2), 4 scatter(s2),
    //   5 mlp(main), 6 edge(main, after join)
    // g_cnt is zeroed by scan_kernel itself (BSS-zero at load).
    cudaMemsetAsync(out, 0, (size_t)out_size * sizeof(float), 0);
    cudaEventRecord(ev0, 0);
    cudaStreamWaitEvent(s2, ev0, 0);

    hist_kernel<<<(E + 255) / 256, 256, 0, s2>>>(idx_i, E);
    scan_kernel<<<1, 1024, 0, s2>>>(A);
    scatter_kernel<<<(E + 255) / 256, 256, 0, s2>>>(idx_i, idx_j, directions, E);
    cudaEventRecord(ev1, s2);

    mlp_kernel<<<(A + 15) / 16, 256>>>(scalars, W1, b1, W2, b2, A);

    // join, then edge-parallel combine with vector reductions
    cudaStreamWaitEvent(0, ev1, 0);
    edge_kernel<<<(E + (8 * EPW) - 1) / (8 * EPW), 256>>>(
        vectors, Wr, br, out_v, out_s, E);
}

// round 15
// speedup vs baseline: 1.1433x; 1.1433x over previous
#include <cuda_runtime.h>
#include <math.h>

#define FF    128
#define F3    384
#define NRBF  20
#define AMAX  50000
#define EMAX  500000
#define PI_F  3.14159265358979323846f
#define RCUT  5.0f
#define KPI   (PI_F / RCUT)

typedef unsigned long long u64;

// scratch (device globals: allocation-free)
__device__ float      g_sbuf[AMAX * F3];   // node MLP output [A,384]
__device__ int        g_cnt[AMAX];
__device__ int        g_cur[AMAX];
__device__ int        g_ii[EMAX];
__device__ int        g_jj[EMAX];
__device__ float      g_dir[EMAX * 3];
__device__ ulonglong2 g_W1q[32 * FF];      // W1 4k-chunks packed f32x2
__device__ ulonglong2 g_W2q[32 * F3];      // W2 4k-chunks packed f32x2

// ---- packed fp32x2 helpers -------------------------------------------------
__device__ __forceinline__ u64 pk2(float lo, float hi) {
    u64 r; asm("mov.b64 %0, {%1, %2};" : "=l"(r) : "f"(lo), "f"(hi)); return r;
}
__device__ __forceinline__ u64 fma2(u64 a, u64 b, u64 c) {
    u64 d; asm("fma.rn.f32x2 %0, %1, %2, %3;" : "=l"(d) : "l"(a), "l"(b), "l"(c));
    return d;
}
__device__ __forceinline__ float2 upk2(u64 v) {
    float2 f; asm("mov.b64 {%0, %1}, %2;" : "=f"(f.x), "=f"(f.y) : "l"(v)); return f;
}

// ---------------------------------------------------------------------------
__global__ void pack_kernel(const float* __restrict__ W1,
                            const float* __restrict__ W2) {
    int t = blockIdx.x * blockDim.x + threadIdx.x;   // 0 .. 32*512-1
    if (t < 32 * FF) {
        int k4 = t >> 7, n = t & 127;
        ulonglong2 v;
        v.x = pk2(W1[(4 * k4 + 0) * FF + n], W1[(4 * k4 + 1) * FF + n]);
        v.y = pk2(W1[(4 * k4 + 2) * FF + n], W1[(4 * k4 + 3) * FF + n]);
        g_W1q[t] = v;
    }
    int t2 = t - 32 * FF;
    if (t2 >= 0 && t2 < 32 * F3) {
        int k4 = t2 / F3, cn = t2 % F3;
        ulonglong2 v;
        v.x = pk2(W2[(4 * k4 + 0) * F3 + cn], W2[(4 * k4 + 1) * F3 + cn]);
        v.y = pk2(W2[(4 * k4 + 2) * F3 + cn], W2[(4 * k4 + 3) * F3 + cn]);
        g_W2q[t2] = v;
    }
}

__global__ void hist_kernel(const int* __restrict__ idx_i, int E) {
    int e = blockIdx.x * blockDim.x + threadIdx.x;
    if (e < E) atomicAdd(&g_cnt[idx_i[e]], 1);
}

// single-block exclusive scan over g_cnt -> g_cur (1024 threads)
__global__ __launch_bounds__(1024) void scan_kernel(int A) {
    __shared__ int wsum[32];
    __shared__ int s_carry;
    const int tid = threadIdx.x, lane = tid & 31, w = tid >> 5;
    if (tid == 0) s_carry = 0;
    __syncthreads();
    for (int base = 0; base < A; base += 1024) {
        int v = (base + tid < A) ? g_cnt[base + tid] : 0;
        int incl = v;
#pragma unroll
        for (int d = 1; d < 32; d <<= 1) {
            int t = __shfl_up_sync(0xffffffffu, incl, d);
            if (lane >= d) incl += t;
        }
        if (lane == 31) wsum[w] = incl;
        __syncthreads();
        if (w == 0) {
            int s = wsum[lane];
#pragma unroll
            for (int d = 1; d < 32; d <<= 1) {
                int t = __shfl_up_sync(0xffffffffu, s, d);
                if (lane >= d) s += t;
            }
            wsum[lane] = s;
        }
        __syncthreads();
        int blockIncl = incl + (w > 0 ? wsum[w - 1] : 0);
        int carry = s_carry;
        if (base + tid < A) g_cur[base + tid] = carry + blockIncl - v;
        __syncthreads();
        if (tid == 1023) s_carry = carry + blockIncl;
        __syncthreads();
    }
}

__global__ void scatter_kernel(const int* __restrict__ idx_i,
                               const int* __restrict__ idx_j,
                               const float* __restrict__ directions, int E) {
    int e = blockIdx.x * blockDim.x + threadIdx.x;
    if (e >= E) return;
    int i = idx_i[e];
    int pos = atomicAdd(&g_cur[i], 1);
    g_ii[pos] = i;
    g_jj[pos] = idx_j[e];
    g_dir[(size_t)pos * 3 + 0] = directions[(size_t)e * 3 + 0];
    g_dir[(size_t)pos * 3 + 1] = directions[(size_t)e * 3 + 1];
    g_dir[(size_t)pos * 3 + 2] = directions[(size_t)e * 3 + 2];
}

// ---------------------------------------------------------------------------
// Node MLP: 16 rows/block, 256 threads, FFMA2, PRE-PACKED weights (LDG.128
// instead of 4x scalar LDG.32 per k-chunk; weight-load instrs cut 4x).
__global__ __launch_bounds__(256, 2) void mlp_kernel(
    const float* __restrict__ scalars,
    const float* __restrict__ b1, const float* __restrict__ b2, int A)
{
    __shared__ float sx[16][FF];
    __shared__ float sh[16][FF];
    const int row0 = blockIdx.x * 16;
    const int tid  = threadIdx.x;

    for (int idx = tid; idx < 16 * 32; idx += 256) {
        int m = idx >> 5, c = idx & 31;
        float4 v = make_float4(0.f, 0.f, 0.f, 0.f);
        if (row0 + m < A)
            v = reinterpret_cast<const float4*>(scalars)[(size_t)(row0 + m) * 32 + c];
        *reinterpret_cast<float4*>(&sx[m][c * 4]) = v;
    }
    __syncthreads();

    const int n  = tid & 127;
    const int m0 = (tid >> 7) * 8;

    u64 acc[8];
#pragma unroll
    for (int i = 0; i < 8; i++) acc[i] = 0ull;

#pragma unroll 4
    for (int k4 = 0; k4 < 32; k4++) {            // chunk of 4 k's
        ulonglong2 w = g_W1q[k4 * FF + n];
#pragma unroll
        for (int i = 0; i < 8; i++) {
            ulonglong2 x2 = *reinterpret_cast<const ulonglong2*>(&sx[m0 + i][k4 * 4]);
            acc[i] = fma2(x2.x, w.x, acc[i]);
            acc[i] = fma2(x2.y, w.y, acc[i]);
        }
    }
    {
        float bb = b1[n];
#pragma unroll
        for (int i = 0; i < 8; i++) {
            float2 p = upk2(acc[i]);
            float x = p.x + p.y + bb;
            sh[m0 + i][n] = x / (1.f + __expf(-x));
        }
    }
    __syncthreads();

    u64 a2[8][3];
#pragma unroll
    for (int i = 0; i < 8; i++)
#pragma unroll
        for (int c = 0; c < 3; c++) a2[i][c] = 0ull;

#pragma unroll 2
    for (int k4 = 0; k4 < 32; k4++) {
        ulonglong2 w0 = g_W2q[k4 * F3 + n];
        ulonglong2 w1 = g_W2q[k4 * F3 + 128 + n];
        ulonglong2 w2 = g_W2q[k4 * F3 + 256 + n];
#pragma unroll
        for (int i = 0; i < 8; i++) {
            ulonglong2 h2 = *reinterpret_cast<const ulonglong2*>(&sh[m0 + i][k4 * 4]);
            a2[i][0] = fma2(h2.x, w0.x, a2[i][0]);
            a2[i][0] = fma2(h2.y, w0.y, a2[i][0]);
            a2[i][1] = fma2(h2.x, w1.x, a2[i][1]);
            a2[i][1] = fma2(h2.y, w1.y, a2[i][1]);
            a2[i][2] = fma2(h2.x, w2.x, a2[i][2]);
            a2[i][2] = fma2(h2.y, w2.y, a2[i][2]);
        }
    }
    {
        float c0 = b2[n], c1 = b2[n + 128], c2v = b2[n + 256];
#pragma unroll
        for (int i = 0; i < 8; i++) {
            int row = row0 + m0 + i;
            if (row < A) {
                float2 p0 = upk2(a2[i][0]);
                float2 p1 = upk2(a2[i][1]);
                float2 p2 = upk2(a2[i][2]);
                g_sbuf[(size_t)row * F3 + n]       = p0.x + p0.y + c0;
                g_sbuf[(size_t)row * F3 + n + 128] = p1.x + p1.y + c1;
                g_sbuf[(size_t)row * F3 + n + 256] = p2.x + p2.y + c2v;
            }
        }
    }
}

// ---------------------------------------------------------------------------
__device__ __forceinline__ void red4(float* p, float4 v) {
    asm volatile("red.global.add.v4.f32 [%0], {%1, %2, %3, %4};"
                 :: "l"(p), "f"(v.x), "f"(v.y), "f"(v.z), "f"(v.w)
                 : "memory");
}

#define EPW 4   // edges per warp

// Edge kernel over i-sorted edges: verbatim from the 575.7us champion.
__global__ __launch_bounds__(256, 2) void edge_kernel(
    const float* __restrict__ vectors,
    const float* __restrict__ Wr, const float* __restrict__ br,
    float* __restrict__ out_v, float* __restrict__ out_s, int E)
{
    __shared__ float4 swr[NRBF * 96];   // Wr [20][384] as float4
    __shared__ float  sbr[F3];

    const int tid = threadIdx.x;
    for (int i2 = tid; i2 < NRBF * 96; i2 += 256)
        swr[i2] = reinterpret_cast<const float4*>(Wr)[i2];
    for (int i2 = tid; i2 < F3; i2 += 256) sbr[i2] = br[i2];
    __syncthreads();

    const int warp = tid >> 5;
    const int lane = tid & 31;
    const int ebase = (blockIdx.x * 8 + warp) * EPW;

    float d0[EPW], d1[EPW], d2[EPW], inv[EPW], fc[EPW], c2r[EPW], scur[EPW], sprev[EPW];
    int   ii[EPW], jj[EPW];
    bool  val[EPW];

#pragma unroll
    for (int e = 0; e < EPW; e++) {
        int ee = ebase + e;
        val[e] = (ee < E);
        d0[e] = 1.f; d1[e] = 0.f; d2[e] = 0.f; ii[e] = 0; jj[e] = 0;
        if (val[e]) {
            d0[e] = g_dir[(size_t)ee * 3 + 0];
            d1[e] = g_dir[(size_t)ee * 3 + 1];
            d2[e] = g_dir[(size_t)ee * 3 + 2];
            ii[e] = g_ii[ee];
            jj[e] = g_jj[ee];
        }
        float nrm = sqrtf(d0[e] * d0[e] + d1[e] * d1[e] + d2[e] * d2[e]);
        inv[e] = 1.f / nrm;
        float x = KPI * nrm;
        float s1, c1;
        __sincosf(x, &s1, &c1);
        c2r[e]   = 2.f * c1;
        scur[e]  = s1;
        sprev[e] = 0.f;
        float delta = nrm - RCUT;
        float mask  = fminf(delta, 0.f) / delta;
        fc[e] = 0.5f * (c1 + 1.f) * mask;
    }

    ulonglong2 aA[EPW], aB[EPW], aC[EPW];
#pragma unroll
    for (int e = 0; e < EPW; e++) {
        aA[e] = make_ulonglong2(0ull, 0ull);
        aB[e] = make_ulonglong2(0ull, 0ull);
        aC[e] = make_ulonglong2(0ull, 0ull);
    }

#pragma unroll
    for (int k = 0; k < NRBF; k++) {
        ulonglong2 wA = *reinterpret_cast<const ulonglong2*>(&swr[k * 96 + lane]);
        ulonglong2 wB = *reinterpret_cast<const ulonglong2*>(&swr[k * 96 + 32 + lane]);
        ulonglong2 wC = *reinterpret_cast<const ulonglong2*>(&swr[k * 96 + 64 + lane]);
#pragma unroll
        for (int e = 0; e < EPW; e++) {
            float s = scur[e];
            u64 sd = pk2(s, s);
            aA[e].x = fma2(wA.x, sd, aA[e].x);
            aA[e].y = fma2(wA.y, sd, aA[e].y);
            aB[e].x = fma2(wB.x, sd, aB[e].x);
            aB[e].y = fma2(wB.y, sd, aB[e].y);
            aC[e].x = fma2(wC.x, sd, aC[e].x);
            aC[e].y = fma2(wC.y, sd, aC[e].y);
            float t = c2r[e] * s - sprev[e];
            sprev[e] = s;
            scur[e]  = t;
        }
    }

    const int f4 = lane * 4;
    float4 brA = *reinterpret_cast<const float4*>(&sbr[f4]);
    float4 brB = *reinterpret_cast<const float4*>(&sbr[128 + f4]);
    float4 brC = *reinterpret_cast<const float4*>(&sbr[256 + f4]);

#pragma unroll
    for (int e = 0; e < EPW; e++) {
        if (!val[e]) continue;
        float f  = fc[e];
        float sc = f * inv[e];

        float2 pAx = upk2(aA[e].x), pAy = upk2(aA[e].y);
        float2 pBx = upk2(aB[e].x), pBy = upk2(aB[e].y);
        float2 pCx = upk2(aC[e].x), pCy = upk2(aC[e].y);

        float4 rA, rB, rC;
        rA.x = sc * pAx.x + f * brA.x; rA.y = sc * pAx.y + f * brA.y;
        rA.z = sc * pAy.x + f * brA.z; rA.w = sc * pAy.y + f * brA.w;
        rB.x = sc * pBx.x + f * brB.x; rB.y = sc * pBx.y + f * brB.y;
        rB.z = sc * pBy.x + f * brB.z; rB.w = sc * pBy.y + f * brB.w;
        rC.x = sc * pCx.x + f * brC.x; rC.y = sc * pCx.y + f * brC.y;
        rC.z = sc * pCy.x + f * brC.z; rC.w = sc * pCy.y + f * brC.w;

        size_t ib = (size_t)ii[e] * F3 + f4;
        float4 sA = *reinterpret_cast<const float4*>(&g_sbuf[ib]);
        float4 sB = *reinterpret_cast<const float4*>(&g_sbuf[ib + 128]);
        float4 sC = *reinterpret_cast<const float4*>(&g_sbuf[ib + 256]);

        float4 ds, dv1, dv2;
        ds.x  = sA.x * rA.x; ds.y  = sA.y * rA.y; ds.z  = sA.z * rA.z; ds.w  = sA.w * rA.w;
        dv1.x = sB.x * rB.x; dv1.y = sB.y * rB.y; dv1.z = sB.z * rB.z; dv1.w = sB.w * rB.w;
        dv2.x = sC.x * rC.x; dv2.y = sC.y * rC.y; dv2.z = sC.z * rC.z; dv2.w = sC.w * rC.w;

        red4(out_s + (size_t)jj[e] * FF + f4, ds);

        float dh[3];
        dh[0] = d0[e] * inv[e]; dh[1] = d1[e] * inv[e]; dh[2] = d2[e] * inv[e];

        size_t vb = (size_t)ii[e] * F3 + f4;
        size_t ob = (size_t)jj[e] * F3 + f4;
#pragma unroll
        for (int d = 0; d < 3; d++) {
            float4 vv = *reinterpret_cast<const float4*>(&vectors[vb + d * 128]);
            float4 ct;
            ct.x = vv.x * dv1.x + dv2.x * dh[d];
            ct.y = vv.y * dv1.y + dv2.y * dh[d];
            ct.z = vv.z * dv1.z + dv2.z * dh[d];
            ct.w = vv.w * dv1.w + dv2.w * dh[d];
            red4(out_v + ob + d * 128, ct);
        }
    }
}

// ---------------------------------------------------------------------------
extern "C" void kernel_launch(void* const* d_in, const int* in_sizes, int n_in,
                              void* d_out, int out_size) {
    const float* vectors    = (const float*)d_in[0];
    const float* scalars    = (const float*)d_in[1];
    const float* directions = (const float*)d_in[2];
    const int*   idx_i      = (const int*)d_in[3];
    const int*   idx_j      = (const int*)d_in[4];
    const float* W1         = (const float*)d_in[5];
    const float* b1         = (const float*)d_in[6];
    const float* W2         = (const float*)d_in[7];
    const float* b2         = (const float*)d_in[8];
    const float* Wr         = (const float*)d_in[9];
    const float* br         = (const float*)d_in[10];

    const int A = in_sizes[0] / (3 * FF);
    const int E = in_sizes[2] / 3;

    float* out   = (float*)d_out;
    float* out_v = out;                          // delta_v: A x 3 x F
    float* out_s = out + (size_t)A * 3 * FF;     // delta_s: A x 1 x F

    static void* p_cnt = nullptr;
    static cudaStream_t s2 = nullptr;
    static cudaEvent_t ev0 = nullptr, ev1 = nullptr;
    if (!p_cnt) {
        cudaGetSymbolAddress(&p_cnt, g_cnt);
        cudaStreamCreateWithFlags(&s2, cudaStreamNonBlocking);
        cudaEventCreateWithFlags(&ev0, cudaEventDisableTiming);
        cudaEventCreateWithFlags(&ev1, cudaEventDisableTiming);
    }

    // fork: counting-sort chain (by idx_i) on s2; memset+pack+MLP on main
    // (launcher identical to the 575.7us champion, plus pack before mlp)
    cudaEventRecord(ev0, 0);
    cudaStreamWaitEvent(s2, ev0, 0);

    cudaMemsetAsync(p_cnt, 0, (size_t)A * sizeof(int), s2);
    hist_kernel<<<(E + 255) / 256, 256, 0, s2>>>(idx_i, E);
    scan_kernel<<<1, 1024, 0, s2>>>(A);
    scatter_kernel<<<(E + 255) / 256, 256, 0, s2>>>(idx_i, idx_j, directions, E);
    cudaEventRecord(ev1, s2);

    cudaMemsetAsync(out, 0, (size_t)out_size * sizeof(float), 0);
    pack_kernel<<<(32 * (FF + F3) + 255) / 256, 256>>>(W1, W2);
    mlp_kernel<<<(A + 15) / 16, 256>>>(scalars, b1, b2, A);

    // join, then edge-parallel combine with vector reductions
    cudaStreamWaitEvent(0, ev1, 0);
    edge_kernel<<<(E + (8 * EPW) - 1) / (8 * EPW), 256>>>(
        vectors, Wr, br, out_v, out_s, E);
}